// round 2
// baseline (speedup 1.0000x reference)
#include <cuda_runtime.h>

#define SS 2048
#define DD 64
#define BHN 16
#define BM 32
#define BK 64

// Mask dtype runtime flag: 1 = int32 (bool promoted), 0 = uint8/bool bytes.
__device__ int g_mask_i32;

__global__ void detect_mask_dtype(const int* __restrict__ m)
{
    int bad = 0;
    for (int i = threadIdx.x; i < 4096; i += 32) {
        unsigned v = (unsigned)m[i];
        bad |= (v > 1u);
    }
    bad = __any_sync(0xffffffffu, bad);
    if (threadIdx.x == 0) g_mask_i32 = bad ? 0 : 1;
}

// ---------- packed f32x2 helpers (sm_100+; ptxas never auto-generates these) ----------
static __device__ __forceinline__ unsigned long long pk2(float lo, float hi) {
    unsigned long long r;
    asm("mov.b64 %0, {%1, %2};" : "=l"(r) : "f"(lo), "f"(hi));
    return r;
}
static __device__ __forceinline__ void upk2(unsigned long long v, float& lo, float& hi) {
    asm("mov.b64 {%0, %1}, %2;" : "=f"(lo), "=f"(hi) : "l"(v));
}
static __device__ __forceinline__ unsigned long long ffma2(unsigned long long a,
                                                           unsigned long long b,
                                                           unsigned long long c) {
    unsigned long long d;
    asm("fma.rn.f32x2 %0, %1, %2, %3;" : "=l"(d) : "l"(a), "l"(b), "l"(c));
    return d;
}

// ============================================================================
// Pass 1 (fused): per (32-q tile, bh):
//   s = Q K^T       (f32x2 microkernel, K tile transposed+XOR-swizzled in smem)
//   a = mask ? -1e9 : s*scale   -> written RAW into the attn_p output region
//   attn_v += a @ V (f32x2 microkernel; a round-trips through swizzled smem aT)
// Thread layout: 128 threads = 16(tx: 4-wide col groups) x 8(ty: 4-wide q groups)
// ============================================================================
__global__ void __launch_bounds__(128) attn_pass1(
    const float* __restrict__ Qg, const float* __restrict__ Kg,
    const float* __restrict__ Vg, const void* __restrict__ Mg,
    float* __restrict__ outV, float* __restrict__ outA, int writeA)
{
    __shared__ float Qt[DD * BM];   // [d][q]            8 KB
    __shared__ float Kt[DD * BK];   // [d][k] swizzled  16 KB
    __shared__ float Vs[BK * DD];   // [k][d]           16 KB
    __shared__ float aT[BK * BM];   // [k][q] swizzled   8 KB   (total 48 KB)

    const int tid = threadIdx.x;
    const int tx  = tid & 15;   // 0..15
    const int ty  = tid >> 4;   // 0..7
    const int bh  = blockIdx.y;
    const int q0  = blockIdx.x * BM;
    const int mI32 = g_mask_i32;

    const float* Qp = Qg + ((size_t)bh * SS + q0) * DD;
    const float* Kp = Kg + (size_t)bh * SS * DD;
    const float* Vp = Vg + (size_t)bh * SS * DD;
    const size_t moff = ((size_t)bh * SS + q0) * (size_t)SS;
    const unsigned char* Mp8 = (const unsigned char*)Mg + moff;
    const int* Mp32 = (const int*)Mg + moff;
    float* Ap = outA + ((size_t)bh * SS + q0) * (size_t)SS;
    float* Vo = outV + ((size_t)bh * SS + q0) * DD;

    // Load Q tile transposed: Qt[d][q]
    for (int i = tid; i < BM * DD / 4; i += 128) {
        int q = i >> 4, d4 = i & 15;
        float4 v = *(const float4*)(Qp + q * DD + d4 * 4);
        Qt[(d4 * 4 + 0) * BM + q] = v.x;
        Qt[(d4 * 4 + 1) * BM + q] = v.y;
        Qt[(d4 * 4 + 2) * BM + q] = v.z;
        Qt[(d4 * 4 + 3) * BM + q] = v.w;
    }

    unsigned long long accv[4][2];
#pragma unroll
    for (int j = 0; j < 4; j++) { accv[j][0] = 0ull; accv[j][1] = 0ull; }

    for (int kt = 0; kt < SS / BK; kt++) {
        __syncthreads();  // protect smem reuse from previous iteration

        // Fill K tile (transposed, float4-granule XOR swizzle) and V tile.
        for (int i = tid; i < BK * DD / 4; i += 128) {
            int k = i >> 4, d4 = i & 15;
            const float4 kv = *(const float4*)(Kp + (size_t)(kt * BK + k) * DD + d4 * 4);
            int col = (((k >> 2) ^ d4) << 2) + (k & 3);
            Kt[(d4 * 4 + 0) * BK + col] = kv.x;
            Kt[(d4 * 4 + 1) * BK + col] = kv.y;
            Kt[(d4 * 4 + 2) * BK + col] = kv.z;
            Kt[(d4 * 4 + 3) * BK + col] = kv.w;
            const float4 vv4 = *(const float4*)(Vp + (size_t)(kt * BK + k) * DD + d4 * 4);
            *(float4*)(Vs + k * DD + d4 * 4) = vv4;
        }
        __syncthreads();

        // ---- s = Q K^T  (64-deep inner product over d) ----
        unsigned long long accs[4][2];
#pragma unroll
        for (int j = 0; j < 4; j++) { accs[j][0] = 0ull; accs[j][1] = 0ull; }

#pragma unroll 8
        for (int d = 0; d < DD; d++) {
            unsigned long long ap0 = *(const unsigned long long*)(Qt + d * BM + ty * 4);
            unsigned long long ap1 = *(const unsigned long long*)(Qt + d * BM + ty * 4 + 2);
            float4 b = *(const float4*)(Kt + d * BK + ((tx ^ (d >> 2)) << 2));
            unsigned long long b0 = pk2(b.x, b.x), b1 = pk2(b.y, b.y);
            unsigned long long b2 = pk2(b.z, b.z), b3 = pk2(b.w, b.w);
            accs[0][0] = ffma2(b0, ap0, accs[0][0]); accs[0][1] = ffma2(b0, ap1, accs[0][1]);
            accs[1][0] = ffma2(b1, ap0, accs[1][0]); accs[1][1] = ffma2(b1, ap1, accs[1][1]);
            accs[2][0] = ffma2(b2, ap0, accs[2][0]); accs[2][1] = ffma2(b2, ap1, accs[2][1]);
            accs[3][0] = ffma2(b3, ap0, accs[3][0]); accs[3][1] = ffma2(b3, ap1, accs[3][1]);
        }

        float sv[4][4];  // [j (k offset)][qq]
#pragma unroll
        for (int j = 0; j < 4; j++) {
            upk2(accs[j][0], sv[j][0], sv[j][1]);
            upk2(accs[j][1], sv[j][2], sv[j][3]);
        }

        // ---- mask + scale; write raw a to global; stage aT (swizzled) ----
        const int kb = kt * BK + tx * 4;
        const int k0 = tx * 4;
#pragma unroll
        for (int qq = 0; qq < 4; qq++) {
            const int q = ty * 4 + qq;
            int mx, my, mz, mw;
            if (mI32) {
                int4 mi = *(const int4*)(Mp32 + (size_t)q * SS + kb);
                mx = mi.x; my = mi.y; mz = mi.z; mw = mi.w;
            } else {
                uchar4 mu = *(const uchar4*)(Mp8 + (size_t)q * SS + kb);
                mx = mu.x; my = mu.y; mz = mu.z; mw = mu.w;
            }
            float4 w;
            w.x = mx ? -1e9f : sv[0][qq] * 0.125f;
            w.y = my ? -1e9f : sv[1][qq] * 0.125f;
            w.z = mz ? -1e9f : sv[2][qq] * 0.125f;
            w.w = mw ? -1e9f : sv[3][qq] * 0.125f;
            if (writeA) *(float4*)(Ap + (size_t)q * SS + kb) = w;
            // aT element (k, q) stored at pair ( (q>>1) ^ (k&15) ), elem (q&1)
            aT[(k0 + 0) * BM + ((((q >> 1) ^ ((k0 + 0) & 15))) << 1) + (q & 1)] = w.x;
            aT[(k0 + 1) * BM + ((((q >> 1) ^ ((k0 + 1) & 15))) << 1) + (q & 1)] = w.y;
            aT[(k0 + 2) * BM + ((((q >> 1) ^ ((k0 + 2) & 15))) << 1) + (q & 1)] = w.z;
            aT[(k0 + 3) * BM + ((((q >> 1) ^ ((k0 + 3) & 15))) << 1) + (q & 1)] = w.w;
        }
        __syncthreads();

        // ---- attn_v += a @ V  (64-deep inner product over k) ----
#pragma unroll 8
        for (int k = 0; k < BK; k++) {
            unsigned long long a0 =
                *(const unsigned long long*)(aT + k * BM + (((ty * 2 + 0) ^ (k & 15)) << 1));
            unsigned long long a1 =
                *(const unsigned long long*)(aT + k * BM + (((ty * 2 + 1) ^ (k & 15)) << 1));
            float4 b = *(const float4*)(Vs + k * DD + tx * 4);
            unsigned long long b0 = pk2(b.x, b.x), b1 = pk2(b.y, b.y);
            unsigned long long b2 = pk2(b.z, b.z), b3 = pk2(b.w, b.w);
            accv[0][0] = ffma2(b0, a0, accv[0][0]); accv[0][1] = ffma2(b0, a1, accv[0][1]);
            accv[1][0] = ffma2(b1, a0, accv[1][0]); accv[1][1] = ffma2(b1, a1, accv[1][1]);
            accv[2][0] = ffma2(b2, a0, accv[2][0]); accv[2][1] = ffma2(b2, a1, accv[2][1]);
            accv[3][0] = ffma2(b3, a0, accv[3][0]); accv[3][1] = ffma2(b3, a1, accv[3][1]);
        }
    }

    // ---- write attn_v tile ----
    float vv[4][4];  // [j (d offset)][qq]
#pragma unroll
    for (int j = 0; j < 4; j++) {
        upk2(accv[j][0], vv[j][0], vv[j][1]);
        upk2(accv[j][1], vv[j][2], vv[j][3]);
    }
#pragma unroll
    for (int qq = 0; qq < 4; qq++) {
        float4 w = make_float4(vv[0][qq], vv[1][qq], vv[2][qq], vv[3][qq]);
        *(float4*)(Vo + (size_t)(ty * 4 + qq) * DD + tx * 4) = w;
    }
}

// ============================================================================
// Pass 2: row softmax in place over the attn_p region.
// ============================================================================
__global__ void __launch_bounds__(256) attn_softmax(float* __restrict__ P)
{
    __shared__ float red[8];
    float* p = P + (size_t)blockIdx.x * SS;
    const int t = threadIdx.x;

    float4 v0 = *(const float4*)(p + t * 4);
    float4 v1 = *(const float4*)(p + 1024 + t * 4);

    float m = fmaxf(fmaxf(fmaxf(v0.x, v0.y), fmaxf(v0.z, v0.w)),
                    fmaxf(fmaxf(v1.x, v1.y), fmaxf(v1.z, v1.w)));
#pragma unroll
    for (int o = 16; o > 0; o >>= 1) m = fmaxf(m, __shfl_xor_sync(0xffffffffu, m, o));
    if ((t & 31) == 0) red[t >> 5] = m;
    __syncthreads();
    m = red[0];
#pragma unroll
    for (int i = 1; i < 8; i++) m = fmaxf(m, red[i]);

    float e[8];
    e[0] = __expf(v0.x - m); e[1] = __expf(v0.y - m);
    e[2] = __expf(v0.z - m); e[3] = __expf(v0.w - m);
    e[4] = __expf(v1.x - m); e[5] = __expf(v1.y - m);
    e[6] = __expf(v1.z - m); e[7] = __expf(v1.w - m);

    float s = ((e[0] + e[1]) + (e[2] + e[3])) + ((e[4] + e[5]) + (e[6] + e[7]));
#pragma unroll
    for (int o = 16; o > 0; o >>= 1) s += __shfl_xor_sync(0xffffffffu, s, o);
    __syncthreads();  // everyone done reading red[] for max
    if ((t & 31) == 0) red[t >> 5] = s;
    __syncthreads();
    s = ((red[0] + red[1]) + (red[2] + red[3])) + ((red[4] + red[5]) + (red[6] + red[7]));

    const float inv = 1.0f / s;
    float4 o0 = make_float4(e[0] * inv, e[1] * inv, e[2] * inv, e[3] * inv);
    float4 o1 = make_float4(e[4] * inv, e[5] * inv, e[6] * inv, e[7] * inv);
    *(float4*)(p + t * 4) = o0;
    *(float4*)(p + 1024 + t * 4) = o1;
}

// ============================================================================
extern "C" void kernel_launch(void* const* d_in, const int* in_sizes, int n_in,
                              void* d_out, int out_size)
{
    const float* Q = (const float*)d_in[0];
    const float* K = (const float*)d_in[1];
    const float* V = (const float*)d_in[2];
    const void*  M = d_in[3];

    float* out = (float*)d_out;
    const long long VN = (long long)BHN * SS * DD;            //  2,097,152
    const long long PN = (long long)BHN * SS * (long long)SS; // 67,108,864
    const int writeA = (out_size >= (int)(VN + PN)) ? 1 : 0;

    float* outV = out;
    float* outP = out + VN;   // attn_p region doubles as scratch for raw scores

    detect_mask_dtype<<<1, 32>>>((const int*)M);
    dim3 g1(SS / BM, BHN);
    attn_pass1<<<g1, 128>>>(Q, K, V, M, outV, outP, writeA);
    if (writeA) attn_softmax<<<BHN * SS, 256>>>(outP);
}